// round 7
// baseline (speedup 1.0000x reference)
#include <cuda_runtime.h>
#include <cstdint>

// ============================================================
// Scratch (no allocs allowed)
// ============================================================
#define N_MAX 50048
__device__ float g_send_agg[N_MAX * 32];
__device__ float g_recv_agg[N_MAX * 32];
__device__ float g_e2g[64 * 32];
__device__ float g_n2g[64 * 32];
// transposed [n][k], tf32-rounded weight images
__device__ float g_ew1[128 * 128];
__device__ float g_ew2[32 * 128];
__device__ float g_nw1[128 * 128];
__device__ float g_nw2[32 * 128];

__device__ __forceinline__ uint32_t tf32r(float x) {
    uint32_t u;
    asm("cvt.rna.tf32.f32 %0, %1;" : "=r"(u) : "f"(x));
    return u;
}
__device__ __forceinline__ void red_add_v4(float* p, float a, float b, float c, float d) {
    asm volatile("red.global.add.v4.f32 [%0], {%1, %2, %3, %4};"
                 :: "l"(p), "f"(a), "f"(b), "f"(c), "f"(d) : "memory");
}
__device__ __forceinline__ void mma_tf32(float* d, const uint32_t* a, const uint32_t* b) {
    asm volatile(
        "mma.sync.aligned.m16n8k8.row.col.f32.tf32.tf32.f32 "
        "{%0,%1,%2,%3}, {%4,%5,%6,%7}, {%8,%9}, {%0,%1,%2,%3};"
        : "+f"(d[0]), "+f"(d[1]), "+f"(d[2]), "+f"(d[3])
        : "r"(a[0]), "r"(a[1]), "r"(a[2]), "r"(a[3]), "r"(b[0]), "r"(b[1]));
}
__device__ __forceinline__ uint32_t smem_u32(const void* p) {
    uint32_t a;
    asm("{ .reg .u64 t; cvta.to.shared.u64 t, %1; cvt.u32.u64 %0, t; }" : "=r"(a) : "l"(p));
    return a;
}
#define LDSM_X4(r0, r1, r2, r3, addr) \
    asm volatile("ldmatrix.sync.aligned.m8n8.x4.shared.b16 {%0,%1,%2,%3}, [%4];" \
                 : "=r"(r0), "=r"(r1), "=r"(r2), "=r"(r3) : "r"(addr))

// ============================================================
// SMEM layout (float offsets).  Row stride 132 -> conflict-free LDSM phases
// ============================================================
#define XSTR 132
#define OFF_X    0                      // 128 x 132
#define OFF_W1   (OFF_X  + 128 * XSTR)  // 128 x 132  (W1^T: [n][k])
#define OFF_W2   (OFF_W1 + 128 * XSTR)  // 32 x 132   (W2^T: [n][k])
#define OFF_Y    (OFF_W2 + 32 * XSTR)   // 128 x 33
#define YSTR 33
#define OFF_B1   (OFF_Y + 128 * YSTR)
#define OFF_B2   (OFF_B1 + 128)
#define OFF_GAM  (OFF_B2 + 32)
#define OFF_BET  (OFF_GAM + 32)
#define OFF_IDXA (OFF_BET + 32)         // 2 x 128 ints (double buffer)
#define OFF_IDXB (OFF_IDXA + 256)
#define OFF_IDXC (OFF_IDXB + 256)
#define OFF_PS   (OFF_IDXC + 256)       // 256 partial sums
#define OFF_PS2  (OFF_PS + 256)
#define SMEM_FLOATS (OFF_PS2 + 256)
#define SMEM_BYTES  (SMEM_FLOATS * 4)

#define GRID_P 148

// ============================================================
// Weight prep: W[k][n] -> W^T [n][k], tf32-rounded
// ============================================================
__global__ void prep_kernel(const float* eW1, const float* eW2,
                            const float* nW1, const float* nW2)
{
    int tid = blockIdx.x * blockDim.x + threadIdx.x;
    int nth = gridDim.x * blockDim.x;
    for (int i = tid; i < 128 * 128; i += nth) {
        int k = i >> 7, n = i & 127;
        ((uint32_t*)g_ew1)[n * 128 + k] = tf32r(eW1[i]);
        ((uint32_t*)g_nw1)[n * 128 + k] = tf32r(nW1[i]);
    }
    for (int i = tid; i < 128 * 32; i += nth) {
        int k = i >> 5, n = i & 31;
        ((uint32_t*)g_ew2)[n * 128 + k] = tf32r(eW2[i]);
        ((uint32_t*)g_nw2)[n * 128 + k] = tf32r(nW2[i]);
    }
}

// ============================================================
// Persistent fused MLP kernel with register-prefetch pipelining.
// MODE 0 = edge model, 1 = node model.  256 threads = 8 warps.
// ============================================================
template <int MODE>
__global__ __launch_bounds__(256, 1)
void mlp_kernel(const float* __restrict__ src_main,
                const float* __restrict__ node_attr,
                const float* __restrict__ global_attr,
                const int*   __restrict__ edge_index,
                const int*   __restrict__ batch,
                const float* __restrict__ w1img, const float* __restrict__ w2img,
                const float* __restrict__ b1g, const float* __restrict__ b2g,
                const float* __restrict__ gamg, const float* __restrict__ betg,
                float* __restrict__ out, int count, int E)
{
    extern __shared__ float sm[];
    float* Xs  = sm + OFF_X;
    float* W1s = sm + OFF_W1;
    float* W2s = sm + OFF_W2;
    float* Ys  = sm + OFF_Y;
    float* b1s = sm + OFF_B1;
    float* b2s = sm + OFF_B2;
    float* gams = sm + OFF_GAM;
    float* bets = sm + OFF_BET;
    int* idxA = (int*)(sm + OFF_IDXA);
    int* idxB = (int*)(sm + OFF_IDXB);
    int* idxC = (int*)(sm + OFF_IDXC);
    float* ps  = sm + OFF_PS;
    float* ps2 = sm + OFF_PS2;

    const int tid  = threadIdx.x;
    const int wid  = tid >> 5;
    const int lane = tid & 31;
    const int lt   = lane & 3;

    // ldmatrix per-lane source row/col offsets
    const int m4    = lane >> 3;
    const int aRow  = ((m4 & 1) << 3) + (lane & 7);
    const int aKoff = (m4 >> 1) << 2;
    const int bNrow = ((m4 >> 1) << 3) + (lane & 7);
    const int bKoff = (m4 & 1) << 2;

    const uint32_t xs_u  = smem_u32(Xs);
    const uint32_t w1_u  = smem_u32(W1s);
    const uint32_t w2_u  = smem_u32(W2s);

    // gather mapping: thread covers edges e_sub+32u, chunk q
    const int e_sub = tid >> 3;
    const int q     = tid & 7;

    // ---- one-time: stage weights (restride 128 -> 132) ----
    for (int i = tid; i < 128 * 32; i += 256) {
        int n = i >> 5, kq = i & 31;
        float4 v = ((const float4*)w1img)[n * 32 + kq];
        *(float4*)&W1s[n * XSTR + kq * 4] = v;
    }
    for (int i = tid; i < 32 * 32; i += 256) {
        int n = i >> 5, kq = i & 31;
        float4 v = ((const float4*)w2img)[n * 32 + kq];
        *(float4*)&W2s[n * XSTR + kq * 4] = v;
    }
    if (tid < 128) b1s[tid] = b1g[tid];
    if (tid < 32) {
        b2s[tid]  = b2g[tid];
        gams[tid] = gamg[tid];
        bets[tid] = betg[tid];
    }
    __syncthreads();

    const int ntiles = (count + 127) >> 7;
    const int step   = gridDim.x;

    // prefetch state (registers)
    float4 pv0[4], pv1[4], pv2[4], pv3[4];
    int pr[4], pc[4], pg[4];

    // ---- prefetch lambda: issue idx + gather LDGs for tile tt ----
    auto PREFETCH = [&](int tt, bool en) {
#pragma unroll
        for (int u = 0; u < 4; u++) {
            int e = e_sub + 32 * u;
            int g = (tt << 7) + e;
            pr[u] = 0; pc[u] = 0;
            bool ok = en && g < count;
            if (MODE == 0) {
                if (ok) { pr[u] = edge_index[g]; pc[u] = edge_index[E + g]; }
            } else {
                if (ok) { pr[u] = batch[g]; }
            }
        }
        if (MODE == 0) {
#pragma unroll
            for (int u = 0; u < 4; u++) pg[u] = batch[pr[u]];
        }
#pragma unroll
        for (int u = 0; u < 4; u++) {
            int e = e_sub + 32 * u;
            int g = (tt << 7) + e;
            float4 z = make_float4(0.f, 0.f, 0.f, 0.f);
            pv0[u] = z; pv1[u] = z; pv2[u] = z; pv3[u] = z;
            bool ok = en && g < count;
            if (ok) {
                if (MODE == 0) {
                    pv0[u] = *(const float4*)(node_attr + (size_t)pc[u] * 32 + q * 4);
                    pv1[u] = *(const float4*)(node_attr + (size_t)pr[u] * 32 + q * 4);
                    pv2[u] = *(const float4*)(src_main + (size_t)g * 32 + q * 4);
                    pv3[u] = *(const float4*)(global_attr + (size_t)pg[u] * 32 + q * 4);
                } else {
                    pv0[u] = *(const float4*)(src_main + (size_t)g * 32 + q * 4);
                    pv1[u] = *(const float4*)(global_attr + (size_t)pr[u] * 32 + q * 4);
                    pv2[u] = *(const float4*)(g_recv_agg + (size_t)g * 32 + q * 4);
                    pv3[u] = *(const float4*)(g_send_agg + (size_t)g * 32 + q * 4);
                }
            }
        }
    };

    int buf = 0;
    if (blockIdx.x < ntiles) PREFETCH(blockIdx.x, true);

    for (int t = blockIdx.x; t < ntiles; t += step) {
        const int t0 = t << 7;

        // ---- commit prefetched X(t) into SMEM (tf32-rounded) + idx ----
#pragma unroll
        for (int u = 0; u < 4; u++) {
            int e = e_sub + 32 * u;
            float* row = Xs + e * XSTR + q * 4;
            uint4 w;
            w.x = tf32r(pv0[u].x); w.y = tf32r(pv0[u].y); w.z = tf32r(pv0[u].z); w.w = tf32r(pv0[u].w);
            *(uint4*)(row) = w;
            w.x = tf32r(pv1[u].x); w.y = tf32r(pv1[u].y); w.z = tf32r(pv1[u].z); w.w = tf32r(pv1[u].w);
            *(uint4*)(row + 32) = w;
            w.x = tf32r(pv2[u].x); w.y = tf32r(pv2[u].y); w.z = tf32r(pv2[u].z); w.w = tf32r(pv2[u].w);
            *(uint4*)(row + 64) = w;
            w.x = tf32r(pv3[u].x); w.y = tf32r(pv3[u].y); w.z = tf32r(pv3[u].z); w.w = tf32r(pv3[u].w);
            *(uint4*)(row + 96) = w;
            if (q == 0) {
                idxA[buf * 128 + e] = pr[u];
                if (MODE == 0) {
                    idxB[buf * 128 + e] = pc[u];
                    idxC[buf * 128 + e] = pg[u];
                }
            }
        }
        __syncthreads();

        // ---- issue prefetch for next tile (hides under GEMM1) ----
        {
            int tn = t + step;
            PREFETCH(tn, tn < ntiles);
        }

        // ================= GEMM1: H = relu(X @ W1 + b1) =================
        {
            const int rbase = 32 * (wid >> 1);
            const int nbase = 64 * (wid & 1);
            const uint32_t aBase0 = xs_u + (uint32_t)(((rbase + aRow) * XSTR + aKoff) * 4);
            const uint32_t aBase1 = aBase0 + 16u * XSTR * 4u;
            const uint32_t bBaseW1 = w1_u + (uint32_t)(((nbase + bNrow) * XSTR + bKoff) * 4);

            float acc[2][8][4];
#pragma unroll
            for (int mb = 0; mb < 2; mb++)
#pragma unroll
                for (int nb = 0; nb < 8; nb++)
#pragma unroll
                    for (int f = 0; f < 4; f++) acc[mb][nb][f] = 0.f;

#pragma unroll
            for (int s = 0; s < 16; s++) {
                const uint32_t kb = 32u * s;
                uint32_t a[2][4];
                LDSM_X4(a[0][0], a[0][1], a[0][2], a[0][3], aBase0 + kb);
                LDSM_X4(a[1][0], a[1][1], a[1][2], a[1][3], aBase1 + kb);
                uint32_t b[8][2];
#pragma unroll
                for (int p = 0; p < 4; p++) {
                    LDSM_X4(b[2 * p][0], b[2 * p][1], b[2 * p + 1][0], b[2 * p + 1][1],
                            bBaseW1 + (uint32_t)(16 * p * XSTR * 4) + kb);
                }
#pragma unroll
                for (int mb = 0; mb < 2; mb++)
#pragma unroll
                    for (int nb = 0; nb < 8; nb++)
                        mma_tf32(acc[mb][nb], a[mb], b[nb]);
            }
            __syncthreads();   // all X/W1 reads done before H overwrites Xs

            const int lg = lane >> 2;
#pragma unroll
            for (int nb = 0; nb < 8; nb++) {
                const int c0 = nbase + 8 * nb + 2 * lt;
                const float bb0 = b1s[c0], bb1 = b1s[c0 + 1];
#pragma unroll
                for (int mb = 0; mb < 2; mb++) {
                    const int r0 = rbase + 16 * mb + lg;
                    uint32_t h0 = tf32r(fmaxf(acc[mb][nb][0] + bb0, 0.f));
                    uint32_t h1 = tf32r(fmaxf(acc[mb][nb][1] + bb1, 0.f));
                    uint32_t h2 = tf32r(fmaxf(acc[mb][nb][2] + bb0, 0.f));
                    uint32_t h3 = tf32r(fmaxf(acc[mb][nb][3] + bb1, 0.f));
                    *(uint2*)&Xs[r0 * XSTR + c0]       = make_uint2(h0, h1);
                    *(uint2*)&Xs[(r0 + 8) * XSTR + c0] = make_uint2(h2, h3);
                }
            }
        }
        __syncthreads();

        // ================= GEMM2: Y = relu(H @ W2 + b2) =================
        {
            const int rbase = 32 * (wid >> 1);
            const int nbase = 16 * (wid & 1);
            const uint32_t aBase0 = xs_u + (uint32_t)(((rbase + aRow) * XSTR + aKoff) * 4);
            const uint32_t aBase1 = aBase0 + 16u * XSTR * 4u;
            const uint32_t bBaseW2 = w2_u + (uint32_t)(((nbase + bNrow) * XSTR + bKoff) * 4);

            float acc[2][2][4];
#pragma unroll
            for (int mb = 0; mb < 2; mb++)
#pragma unroll
                for (int nb = 0; nb < 2; nb++)
#pragma unroll
                    for (int f = 0; f < 4; f++) acc[mb][nb][f] = 0.f;

#pragma unroll
            for (int s = 0; s < 16; s++) {
                const uint32_t kb = 32u * s;
                uint32_t a[2][4];
                LDSM_X4(a[0][0], a[0][1], a[0][2], a[0][3], aBase0 + kb);
                LDSM_X4(a[1][0], a[1][1], a[1][2], a[1][3], aBase1 + kb);
                uint32_t b[2][2];
                LDSM_X4(b[0][0], b[0][1], b[1][0], b[1][1], bBaseW2 + kb);
#pragma unroll
                for (int mb = 0; mb < 2; mb++)
#pragma unroll
                    for (int nb = 0; nb < 2; nb++)
                        mma_tf32(acc[mb][nb], a[mb], b[nb]);
            }

            const int lg = lane >> 2;
#pragma unroll
            for (int nb = 0; nb < 2; nb++) {
                const int c0 = nbase + 8 * nb + 2 * lt;
                const float bb0 = b2s[c0], bb1 = b2s[c0 + 1];
#pragma unroll
                for (int mb = 0; mb < 2; mb++) {
                    const int r0 = rbase + 16 * mb + lg;
                    Ys[r0 * YSTR + c0]           = fmaxf(acc[mb][nb][0] + bb0, 0.f);
                    Ys[r0 * YSTR + c0 + 1]       = fmaxf(acc[mb][nb][1] + bb1, 0.f);
                    Ys[(r0 + 8) * YSTR + c0]     = fmaxf(acc[mb][nb][2] + bb0, 0.f);
                    Ys[(r0 + 8) * YSTR + c0 + 1] = fmaxf(acc[mb][nb][3] + bb1, 0.f);
                }
            }
        }
        __syncthreads();

        // ========= LN (split 16/16 across thread pairs) + store + reds =========
        float yv[16];
        {
            const int row = tid & 127, half = tid >> 7;
            const float* yb = Ys + row * YSTR + half * 16;
            float s = 0.f, s2 = 0.f;
#pragma unroll
            for (int j = 0; j < 16; j++) {
                float v = yb[j];
                yv[j] = v;
                s += v;
                s2 = fmaf(v, v, s2);
            }
            ps[tid] = s;
            ps2[tid] = s2;
        }
        __syncthreads();
        {
            const int row = tid & 127, half = tid >> 7;
            const int g = t0 + row;
            if (g < count) {
                float s  = ps[tid] + ps[tid ^ 128];
                float s2 = ps2[tid] + ps2[tid ^ 128];
                float mu = s * (1.f / 32.f);
                float rs = rsqrtf(fmaxf(s2 * (1.f / 32.f) - mu * mu, 0.f) + 1e-5f);
                const int cb = half * 16;
#pragma unroll
                for (int j = 0; j < 16; j++)
                    yv[j] = (yv[j] - mu) * rs * gams[cb + j] + bets[cb + j];

                float4* op = (float4*)(out + (size_t)g * 32 + cb);
#pragma unroll
                for (int j = 0; j < 4; j++)
                    op[j] = make_float4(yv[4 * j], yv[4 * j + 1], yv[4 * j + 2], yv[4 * j + 3]);

                if (MODE == 0) {
                    float* psend = g_send_agg + (size_t)idxA[buf * 128 + row] * 32 + cb;
                    float* precv = g_recv_agg + (size_t)idxB[buf * 128 + row] * 32 + cb;
                    float* pglob = g_e2g + (size_t)idxC[buf * 128 + row] * 32 + cb;
#pragma unroll
                    for (int j = 0; j < 4; j++) {
                        red_add_v4(psend + 4 * j, yv[4 * j], yv[4 * j + 1], yv[4 * j + 2], yv[4 * j + 3]);
                        red_add_v4(precv + 4 * j, yv[4 * j], yv[4 * j + 1], yv[4 * j + 2], yv[4 * j + 3]);
                        red_add_v4(pglob + 4 * j, yv[4 * j], yv[4 * j + 1], yv[4 * j + 2], yv[4 * j + 3]);
                    }
                } else {
                    float* pglob = g_n2g + (size_t)idxA[buf * 128 + row] * 32 + cb;
#pragma unroll
                    for (int j = 0; j < 4; j++)
                        red_add_v4(pglob + 4 * j, yv[4 * j], yv[4 * j + 1], yv[4 * j + 2], yv[4 * j + 3]);
                }
            }
        }
        buf ^= 1;
        // no sync needed: next commit touches Xs (idle) and idx buf^1
    }
}

// ============================================================
// Global model (tiny)
// ============================================================
__global__ __launch_bounds__(128)
void global_kernel(const float* __restrict__ global_attr,
                   const float* __restrict__ W1, const float* __restrict__ b1,
                   const float* __restrict__ W2, const float* __restrict__ b2,
                   float* __restrict__ out_glob)
{
    __shared__ float gin[96];
    __shared__ float hs[128];
    const int g = blockIdx.x, tid = threadIdx.x;
    if (tid < 32) {
        gin[tid]      = g_n2g[g * 32 + tid];
        gin[32 + tid] = g_e2g[g * 32 + tid];
        gin[64 + tid] = global_attr[g * 32 + tid];
    }
    __syncthreads();
    float acc = b1[tid];
#pragma unroll 8
    for (int k = 0; k < 96; k++)
        acc = fmaf(gin[k], W1[k * 128 + tid], acc);
    hs[tid] = fmaxf(acc, 0.f);
    __syncthreads();
    if (tid < 32) {
        float a2 = b2[tid];
#pragma unroll 8
        for (int l = 0; l < 128; l++)
            a2 = fmaf(hs[l], W2[l * 32 + tid], a2);
        out_glob[g * 32 + tid] = fmaxf(a2, 0.f);
    }
}

// ============================================================
// launch
// ============================================================
extern "C" void kernel_launch(void* const* d_in, const int* in_sizes, int n_in,
                              void* d_out, int out_size)
{
    const float* edge_attr   = (const float*)d_in[0];
    const float* node_attr   = (const float*)d_in[1];
    const float* global_attr = (const float*)d_in[2];
    const int*   edge_index  = (const int*)d_in[3];
    const int*   batch       = (const int*)d_in[4];
    const float* eW1 = (const float*)d_in[5];
    const float* eb1 = (const float*)d_in[6];
    const float* eW2 = (const float*)d_in[7];
    const float* eb2 = (const float*)d_in[8];
    const float* eg  = (const float*)d_in[9];
    const float* eB  = (const float*)d_in[10];
    const float* nW1 = (const float*)d_in[11];
    const float* nb1 = (const float*)d_in[12];
    const float* nW2 = (const float*)d_in[13];
    const float* nb2 = (const float*)d_in[14];
    const float* ng  = (const float*)d_in[15];
    const float* nB  = (const float*)d_in[16];
    const float* gW1 = (const float*)d_in[17];
    const float* gb1 = (const float*)d_in[18];
    const float* gW2 = (const float*)d_in[19];
    const float* gb2 = (const float*)d_in[20];

    const int E = in_sizes[0] / 32;
    const int N = in_sizes[1] / 32;
    const int G = in_sizes[2] / 32;

    float* out      = (float*)d_out;
    float* out_edge = out;
    float* out_node = out + (size_t)E * 32;
    float* out_glob = out + (size_t)(E + N) * 32;

    void* p;
    cudaGetSymbolAddress(&p, g_send_agg);
    cudaMemsetAsync(p, 0, (size_t)N * 32 * sizeof(float));
    cudaGetSymbolAddress(&p, g_recv_agg);
    cudaMemsetAsync(p, 0, (size_t)N * 32 * sizeof(float));
    cudaGetSymbolAddress(&p, g_e2g);
    cudaMemsetAsync(p, 0, (size_t)G * 32 * sizeof(float));
    cudaGetSymbolAddress(&p, g_n2g);
    cudaMemsetAsync(p, 0, (size_t)G * 32 * sizeof(float));

    prep_kernel<<<8, 256>>>(eW1, eW2, nW1, nW2);

    cudaFuncSetAttribute(mlp_kernel<0>, cudaFuncAttributeMaxDynamicSharedMemorySize, SMEM_BYTES);
    cudaFuncSetAttribute(mlp_kernel<1>, cudaFuncAttributeMaxDynamicSharedMemorySize, SMEM_BYTES);

    float *ew1p, *ew2p, *nw1p, *nw2p;
    cudaGetSymbolAddress((void**)&ew1p, g_ew1);
    cudaGetSymbolAddress((void**)&ew2p, g_ew2);
    cudaGetSymbolAddress((void**)&nw1p, g_nw1);
    cudaGetSymbolAddress((void**)&nw2p, g_nw2);

    mlp_kernel<0><<<GRID_P, 256, SMEM_BYTES>>>(
        edge_attr, node_attr, global_attr, edge_index, batch,
        ew1p, ew2p, eb1, eb2, eg, eB, out_edge, E, E);

    mlp_kernel<1><<<GRID_P, 256, SMEM_BYTES>>>(
        node_attr, node_attr, global_attr, edge_index, batch,
        nw1p, nw2p, nb1, nb2, ng, nB, out_node, N, E);

    global_kernel<<<G, 128>>>(global_attr, gW1, gb1, gW2, gb2, out_glob);
}

// round 9
// speedup vs baseline: 1.1942x; 1.1942x over previous
#include <cuda_runtime.h>
#include <cuda_fp16.h>
#include <cstdint>

// ============================================================
// Scratch (no allocs allowed)
// ============================================================
#define N_MAX 50048
__device__ float g_send_agg[N_MAX * 32];
__device__ float g_recv_agg[N_MAX * 32];
__device__ float g_e2g[64 * 32];
__device__ float g_n2g[64 * 32];
// transposed [n][k], fp16 weight images
__device__ __half g_ew1h[128 * 128];
__device__ __half g_ew2h[32 * 128];
__device__ __half g_nw1h[128 * 128];
__device__ __half g_nw2h[32 * 128];

__device__ __forceinline__ void red_add_v4(float* p, float a, float b, float c, float d) {
    asm volatile("red.global.add.v4.f32 [%0], {%1, %2, %3, %4};"
                 :: "l"(p), "f"(a), "f"(b), "f"(c), "f"(d) : "memory");
}
__device__ __forceinline__ void mma_f16(float* d, const uint32_t* a, const uint32_t* b) {
    asm volatile(
        "mma.sync.aligned.m16n8k16.row.col.f32.f16.f16.f32 "
        "{%0,%1,%2,%3}, {%4,%5,%6,%7}, {%8,%9}, {%0,%1,%2,%3};"
        : "+f"(d[0]), "+f"(d[1]), "+f"(d[2]), "+f"(d[3])
        : "r"(a[0]), "r"(a[1]), "r"(a[2]), "r"(a[3]), "r"(b[0]), "r"(b[1]));
}
__device__ __forceinline__ uint32_t smem_u32(const void* p) {
    uint32_t a;
    asm("{ .reg .u64 t; cvta.to.shared.u64 t, %1; cvt.u32.u64 %0, t; }" : "=r"(a) : "l"(p));
    return a;
}
#define LDSM_X4(r0, r1, r2, r3, addr) \
    asm volatile("ldmatrix.sync.aligned.m8n8.x4.shared.b16 {%0,%1,%2,%3}, [%4];" \
                 : "=r"(r0), "=r"(r1), "=r"(r2), "=r"(r3) : "r"(addr))

__device__ __forceinline__ uint32_t h2u(float x, float y) {
    __half2 h = __floats2half2_rn(x, y);
    return *reinterpret_cast<uint32_t*>(&h);
}

// ============================================================
// SMEM layout (BYTE offsets).
// fp16 rows stride 136 halves = 272 B; 272 mod 128 = 16 ->
// every 8-row ldmatrix phase covers all 32 banks once (conflict-free).
// ============================================================
#define XSTRB 272                      // bytes per fp16 row (136 halves)
#define OFF_X    0                     // 128 x 272B
#define OFF_W1   34816                 // 128 x 272B (W1^T [n][k])
#define OFF_W2   69632                 // 32 x 272B  (W2^T [n][k])
#define OFF_Y    78336                 // 128 x 33 fp32
#define YSTR 33
#define OFF_B1   95232                 // 128 f
#define OFF_B2   95744                 // 32 f
#define OFF_GAM  95872
#define OFF_BET  96000
#define OFF_IDXA 96128                 // 2 x 128 int (double buffer)
#define OFF_IDXB 97152
#define OFF_IDXC 98176
#define OFF_PS   99200                 // 256 f
#define OFF_PS2  100224                // 256 f
#define SMEM_BYTES 101248

#define GRID_P 148

// ============================================================
// Weight prep: W[k][n] -> W^T [n][k], fp16
// ============================================================
__global__ void prep_kernel(const float* eW1, const float* eW2,
                            const float* nW1, const float* nW2)
{
    int tid = blockIdx.x * blockDim.x + threadIdx.x;
    int nth = gridDim.x * blockDim.x;
    for (int i = tid; i < 128 * 128; i += nth) {
        int k = i >> 7, n = i & 127;
        g_ew1h[n * 128 + k] = __float2half_rn(eW1[i]);
        g_nw1h[n * 128 + k] = __float2half_rn(nW1[i]);
    }
    for (int i = tid; i < 128 * 32; i += nth) {
        int k = i >> 5, n = i & 31;
        g_ew2h[n * 128 + k] = __float2half_rn(eW2[i]);
        g_nw2h[n * 128 + k] = __float2half_rn(nW2[i]);
    }
}

// ============================================================
// Persistent fused MLP kernel (fp16 tensor path).
// MODE 0 = edge model, 1 = node model.  256 threads = 8 warps.
// GEMM1: warp w -> rows 32*(w>>1), cols 64*(w&1); 2 mb x 8 nb, 8 ksteps k16
// GEMM2: warp w -> rows 32*(w>>1), cols 16*(w&1); 2 mb x 2 nb, 8 ksteps k16
// ============================================================
template <int MODE>
__global__ __launch_bounds__(256, 1)
void mlp_kernel(const float* __restrict__ src_main,
                const float* __restrict__ node_attr,
                const float* __restrict__ global_attr,
                const int*   __restrict__ edge_index,
                const int*   __restrict__ batch,
                const __half* __restrict__ w1img, const __half* __restrict__ w2img,
                const float* __restrict__ b1g, const float* __restrict__ b2g,
                const float* __restrict__ gamg, const float* __restrict__ betg,
                float* __restrict__ out, int count, int E)
{
    extern __shared__ __align__(16) char smem[];
    float* Ys   = (float*)(smem + OFF_Y);
    float* b1s  = (float*)(smem + OFF_B1);
    float* b2s  = (float*)(smem + OFF_B2);
    float* gams = (float*)(smem + OFF_GAM);
    float* bets = (float*)(smem + OFF_BET);
    int* idxA = (int*)(smem + OFF_IDXA);
    int* idxB = (int*)(smem + OFF_IDXB);
    int* idxC = (int*)(smem + OFF_IDXC);
    float* ps  = (float*)(smem + OFF_PS);
    float* ps2 = (float*)(smem + OFF_PS2);

    const int tid  = threadIdx.x;
    const int wid  = tid >> 5;
    const int lane = tid & 31;
    const int lt   = lane & 3;

    // ldmatrix lane offsets (fp16 m16n8k16)
    const int aRow = lane & 15;                         // A: rows 0-15
    const int aKb  = (lane >> 4) << 4;                  // A: +16B for k8-15 mats
    const int bN   = ((lane >> 4) << 3) | (lane & 7);   // B: n row
    const int bKb  = ((lane >> 3) & 1) << 4;            // B: +16B for k8-15 mats

    const uint32_t xs_u = smem_u32(smem + OFF_X);
    const uint32_t w1_u = smem_u32(smem + OFF_W1);
    const uint32_t w2_u = smem_u32(smem + OFF_W2);

    // gather mapping: thread covers edges e_sub+32u, chunk q (4 floats)
    const int e_sub = tid >> 3;
    const int q     = tid & 7;

    // ---- one-time: stage weights (restride 128 -> 136 halves) ----
    {
        const uint4* s1 = (const uint4*)w1img;          // 2048 x 16B
        for (int i = tid; i < 2048; i += 256) {
            int n = i >> 4, c = i & 15;
            *(uint4*)(smem + OFF_W1 + n * XSTRB + c * 16) = s1[i];
        }
        const uint4* s2 = (const uint4*)w2img;          // 512 x 16B
        for (int i = tid; i < 512; i += 256) {
            int n = i >> 4, c = i & 15;
            *(uint4*)(smem + OFF_W2 + n * XSTRB + c * 16) = s2[i];
        }
    }
    if (tid < 128) b1s[tid] = b1g[tid];
    if (tid < 32) {
        b2s[tid]  = b2g[tid];
        gams[tid] = gamg[tid];
        bets[tid] = betg[tid];
    }
    __syncthreads();

    const int ntiles = (count + 127) >> 7;
    const int step   = gridDim.x;

    // prefetch state (registers)
    float4 pv0[4], pv1[4], pv2[4], pv3[4];
    int pr[4], pc[4], pg[4];

    auto PREFETCH = [&](int tt, bool en) {
#pragma unroll
        for (int u = 0; u < 4; u++) {
            int e = e_sub + 32 * u;
            int g = (tt << 7) + e;
            pr[u] = 0; pc[u] = 0;
            bool ok = en && g < count;
            if (MODE == 0) {
                if (ok) { pr[u] = edge_index[g]; pc[u] = edge_index[E + g]; }
            } else {
                if (ok) { pr[u] = batch[g]; }
            }
        }
        if (MODE == 0) {
#pragma unroll
            for (int u = 0; u < 4; u++) pg[u] = batch[pr[u]];
        }
#pragma unroll
        for (int u = 0; u < 4; u++) {
            int e = e_sub + 32 * u;
            int g = (tt << 7) + e;
            float4 z = make_float4(0.f, 0.f, 0.f, 0.f);
            pv0[u] = z; pv1[u] = z; pv2[u] = z; pv3[u] = z;
            bool ok = en && g < count;
            if (ok) {
                if (MODE == 0) {
                    pv0[u] = *(const float4*)(node_attr + (size_t)pc[u] * 32 + q * 4);
                    pv1[u] = *(const float4*)(node_attr + (size_t)pr[u] * 32 + q * 4);
                    pv2[u] = *(const float4*)(src_main + (size_t)g * 32 + q * 4);
                    pv3[u] = *(const float4*)(global_attr + (size_t)pg[u] * 32 + q * 4);
                } else {
                    pv0[u] = *(const float4*)(src_main + (size_t)g * 32 + q * 4);
                    pv1[u] = *(const float4*)(global_attr + (size_t)pr[u] * 32 + q * 4);
                    pv2[u] = *(const float4*)(g_recv_agg + (size_t)g * 32 + q * 4);
                    pv3[u] = *(const float4*)(g_send_agg + (size_t)g * 32 + q * 4);
                }
            }
        }
    };

    int buf = 0;
    if (blockIdx.x < ntiles) PREFETCH(blockIdx.x, true);

    for (int t = blockIdx.x; t < ntiles; t += step) {
        const int t0 = t << 7;

        // ---- commit prefetched X(t) into SMEM as fp16 + idx ----
#pragma unroll
        for (int u = 0; u < 4; u++) {
            int e = e_sub + 32 * u;
            char* row = smem + OFF_X + e * XSTRB + q * 8;
            *(uint2*)(row)       = make_uint2(h2u(pv0[u].x, pv0[u].y), h2u(pv0[u].z, pv0[u].w));
            *(uint2*)(row + 64)  = make_uint2(h2u(pv1[u].x, pv1[u].y), h2u(pv1[u].z, pv1[u].w));
            *(uint2*)(row + 128) = make_uint2(h2u(pv2[u].x, pv2[u].y), h2u(pv2[u].z, pv2[u].w));
            *(uint2*)(row + 192) = make_uint2(h2u(pv3[u].x, pv3[u].y), h2u(pv3[u].z, pv3[u].w));
            if (q == 0) {
                idxA[buf * 128 + e] = pr[u];
                if (MODE == 0) {
                    idxB[buf * 128 + e] = pc[u];
                    idxC[buf * 128 + e] = pg[u];
                }
            }
        }
        __syncthreads();

        // ---- issue prefetch for next tile (hides under GEMM1) ----
        {
            int tn = t + step;
            PREFETCH(tn, tn < ntiles);
        }

        // ================= GEMM1: H = relu(X @ W1 + b1) =================
        {
            const int rbase = 32 * (wid >> 1);
            const int nbase = 64 * (wid & 1);
            const uint32_t aBase0 = xs_u + (uint32_t)((rbase + aRow) * XSTRB + aKb);
            const uint32_t aBase1 = aBase0 + 16u * XSTRB;
            const uint32_t bBase  = w1_u + (uint32_t)((nbase + bN) * XSTRB + bKb);

            float acc[2][8][4];
#pragma unroll
            for (int mb = 0; mb < 2; mb++)
#pragma unroll
                for (int nb = 0; nb < 8; nb++)
#pragma unroll
                    for (int f = 0; f < 4; f++) acc[mb][nb][f] = 0.f;

#pragma unroll
            for (int s = 0; s < 8; s++) {
                const uint32_t kb = 32u * s;   // 16 halves per kstep
                uint32_t a[2][4];
                LDSM_X4(a[0][0], a[0][1], a[0][2], a[0][3], aBase0 + kb);
                LDSM_X4(a[1][0], a[1][1], a[1][2], a[1][3], aBase1 + kb);
                uint32_t b[8][2];
#pragma unroll
                for (int p = 0; p < 4; p++) {
                    LDSM_X4(b[2 * p][0], b[2 * p][1], b[2 * p + 1][0], b[2 * p + 1][1],
                            bBase + (uint32_t)(16 * p * XSTRB) + kb);
                }
#pragma unroll
                for (int mb = 0; mb < 2; mb++)
#pragma unroll
                    for (int nb = 0; nb < 8; nb++)
                        mma_f16(acc[mb][nb], a[mb], b[nb]);
            }
            __syncthreads();   // all X/W1 reads done before H overwrites X

            // epilogue1: relu(+b1) -> fp16 -> X buffer (H[m][l])
            const int lg = lane >> 2;
#pragma unroll
            for (int nb = 0; nb < 8; nb++) {
                const int c0 = nbase + 8 * nb + 2 * lt;
                const float bb0 = b1s[c0], bb1 = b1s[c0 + 1];
#pragma unroll
                for (int mb = 0; mb < 2; mb++) {
                    const int r0 = rbase + 16 * mb + lg;
                    uint32_t h01 = h2u(fmaxf(acc[mb][nb][0] + bb0, 0.f),
                                       fmaxf(acc[mb][nb][1] + bb1, 0.f));
                    uint32_t h23 = h2u(fmaxf(acc[mb][nb][2] + bb0, 0.f),
                                       fmaxf(acc[mb][nb][3] + bb1, 0.f));
                    *(uint32_t*)(smem + OFF_X + r0 * XSTRB + c0 * 2)       = h01;
                    *(uint32_t*)(smem + OFF_X + (r0 + 8) * XSTRB + c0 * 2) = h23;
                }
            }
        }
        __syncthreads();

        // ================= GEMM2: Y = relu(H @ W2 + b2) =================
        {
            const int rbase = 32 * (wid >> 1);
            const int nbase = 16 * (wid & 1);
            const uint32_t aBase0 = xs_u + (uint32_t)((rbase + aRow) * XSTRB + aKb);
            const uint32_t aBase1 = aBase0 + 16u * XSTRB;
            const uint32_t bBase  = w2_u + (uint32_t)((nbase + bN) * XSTRB + bKb);

            float acc[2][2][4];
#pragma unroll
            for (int mb = 0; mb < 2; mb++)
#pragma unroll
                for (int nb = 0; nb < 2; nb++)
#pragma unroll
                    for (int f = 0; f < 4; f++) acc[mb][nb][f] = 0.f;

#pragma unroll
            for (int s = 0; s < 8; s++) {
                const uint32_t kb = 32u * s;
                uint32_t a[2][4];
                LDSM_X4(a[0][0], a[0][1], a[0][2], a[0][3], aBase0 + kb);
                LDSM_X4(a[1][0], a[1][1], a[1][2], a[1][3], aBase1 + kb);
                uint32_t b[2][2];
                LDSM_X4(b[0][0], b[0][1], b[1][0], b[1][1], bBase + kb);
#pragma unroll
                for (int mb = 0; mb < 2; mb++)
#pragma unroll
                    for (int nb = 0; nb < 2; nb++)
                        mma_f16(acc[mb][nb], a[mb], b[nb]);
            }

            const int lg = lane >> 2;
#pragma unroll
            for (int nb = 0; nb < 2; nb++) {
                const int c0 = nbase + 8 * nb + 2 * lt;
                const float bb0 = b2s[c0], bb1 = b2s[c0 + 1];
#pragma unroll
                for (int mb = 0; mb < 2; mb++) {
                    const int r0 = rbase + 16 * mb + lg;
                    Ys[r0 * YSTR + c0]           = fmaxf(acc[mb][nb][0] + bb0, 0.f);
                    Ys[r0 * YSTR + c0 + 1]       = fmaxf(acc[mb][nb][1] + bb1, 0.f);
                    Ys[(r0 + 8) * YSTR + c0]     = fmaxf(acc[mb][nb][2] + bb0, 0.f);
                    Ys[(r0 + 8) * YSTR + c0 + 1] = fmaxf(acc[mb][nb][3] + bb1, 0.f);
                }
            }
        }
        __syncthreads();

        // ========= LN (split 16/16 across thread pairs) + store + reds =========
        float yv[16];
        {
            const int row = tid & 127, half = tid >> 7;
            const float* yb = Ys + row * YSTR + half * 16;
            float s = 0.f, s2 = 0.f;
#pragma unroll
            for (int j = 0; j < 16; j++) {
                float v = yb[j];
                yv[j] = v;
                s += v;
                s2 = fmaf(v, v, s2);
            }
            ps[tid] = s;
            ps2[tid] = s2;
        }
        __syncthreads();
        {
            const int row = tid & 127, half = tid >> 7;
            const int g = t0 + row;
            if (g < count) {
                float s  = ps[tid] + ps[tid ^ 128];
                float s2 = ps2[tid] + ps2[tid ^ 128];
                float mu = s * (1.f / 32.f);
                float rs = rsqrtf(fmaxf(s2 * (1.f / 32.f) - mu * mu, 0.f) + 1e-5f);
                const int cb = half * 16;
#pragma unroll
                for (int j = 0; j < 16; j++)
                    yv[j] = (yv[j] - mu) * rs * gams[cb + j] + bets[cb + j];

                float4* op = (float4*)(out + (size_t)g * 32 + cb);
#pragma unroll
                for (int j = 0; j < 4; j++)
                    op[j] = make_float4(yv[4 * j], yv[4 * j + 1], yv[4 * j + 2], yv[4 * j + 3]);

                if (MODE == 0) {
                    float* psend = g_send_agg + (size_t)idxA[buf * 128 + row] * 32 + cb;
                    float* precv = g_recv_agg + (size_t)idxB[buf * 128 + row] * 32 + cb;
                    float* pglob = g_e2g + (size_t)idxC[buf * 128 + row] * 32 + cb;
#pragma unroll
                    for (int j = 0; j < 4; j++) {
                        red_add_v4(psend + 4 * j, yv[4 * j], yv[4 * j + 1], yv[4 * j + 2], yv[4 * j + 3]);
                        red_add_v4(precv + 4 * j, yv[4 * j], yv[4 * j + 1], yv[4 * j + 2], yv[4 * j + 3]);
                        red_add_v4(pglob + 4 * j, yv[4 * j], yv[4 * j + 1], yv[4 * j + 2], yv[4 * j + 3]);
                    }
                } else {
                    float* pglob = g_n2g + (size_t)idxA[buf * 128 + row] * 32 + cb;
#pragma unroll
                    for (int j = 0; j < 4; j++)
                        red_add_v4(pglob + 4 * j, yv[4 * j], yv[4 * j + 1], yv[4 * j + 2], yv[4 * j + 3]);
                }
            }
        }
        buf ^= 1;
        // no sync needed: next commit touches X (idle) and idx buf^1
    }
}

// ============================================================
// Global model (tiny)
// ============================================================
__global__ __launch_bounds__(128)
void global_kernel(const float* __restrict__ global_attr,
                   const float* __restrict__ W1, const float* __restrict__ b1,
                   const float* __restrict__ W2, const float* __restrict__ b2,
                   float* __restrict__ out_glob)
{
    __shared__ float gin[96];
    __shared__ float hs[128];
    const int g = blockIdx.x, tid = threadIdx.x;
    if (tid < 32) {
        gin[tid]      = g_n2g[g * 32 + tid];
        gin[32 + tid] = g_e2g[g * 32 + tid];
        gin[64 + tid] = global_attr[g * 32 + tid];
    }
    __syncthreads();
    float acc = b1[tid];
#pragma unroll 8
    for (int k = 0; k < 96; k++)
        acc = fmaf(gin[k], W1[k * 128 + tid], acc);
    hs[tid] = fmaxf(acc, 0.f);
    __syncthreads();
    if (tid < 32) {
        float a2 = b2[tid];
#pragma unroll 8
        for (int l = 0; l < 128; l++)
            a2 = fmaf(hs[l], W2[l * 32 + tid], a2);
        out_glob[g * 32 + tid] = fmaxf(a2, 0.f);
    }
}

// ============================================================
// launch
// ============================================================
extern "C" void kernel_launch(void* const* d_in, const int* in_sizes, int n_in,
                              void* d_out, int out_size)
{
    const float* edge_attr   = (const float*)d_in[0];
    const float* node_attr   = (const float*)d_in[1];
    const float* global_attr = (const float*)d_in[2];
    const int*   edge_index  = (const int*)d_in[3];
    const int*   batch       = (const int*)d_in[4];
    const float* eW1 = (const float*)d_in[5];
    const float* eb1 = (const float*)d_in[6];
    const float* eW2 = (const float*)d_in[7];
    const float* eb2 = (const float*)d_in[8];
    const float* eg  = (const float*)d_in[9];
    const float* eB  = (const float*)d_in[10];
    const float* nW1 = (const float*)d_in[11];
    const float* nb1 = (const float*)d_in[12];
    const float* nW2 = (const float*)d_in[13];
    const float* nb2 = (const float*)d_in[14];
    const float* ng  = (const float*)d_in[15];
    const float* nB  = (const float*)d_in[16];
    const float* gW1 = (const float*)d_in[17];
    const float* gb1 = (const float*)d_in[18];
    const float* gW2 = (const float*)d_in[19];
    const float* gb2 = (const float*)d_in[20];

    const int E = in_sizes[0] / 32;
    const int N = in_sizes[1] / 32;
    const int G = in_sizes[2] / 32;

    float* out      = (float*)d_out;
    float* out_edge = out;
    float* out_node = out + (size_t)E * 32;
    float* out_glob = out + (size_t)(E + N) * 32;

    void* p;
    cudaGetSymbolAddress(&p, g_send_agg);
    cudaMemsetAsync(p, 0, (size_t)N * 32 * sizeof(float));
    cudaGetSymbolAddress(&p, g_recv_agg);
    cudaMemsetAsync(p, 0, (size_t)N * 32 * sizeof(float));
    cudaGetSymbolAddress(&p, g_e2g);
    cudaMemsetAsync(p, 0, (size_t)G * 32 * sizeof(float));
    cudaGetSymbolAddress(&p, g_n2g);
    cudaMemsetAsync(p, 0, (size_t)G * 32 * sizeof(float));

    prep_kernel<<<8, 256>>>(eW1, eW2, nW1, nW2);

    cudaFuncSetAttribute(mlp_kernel<0>, cudaFuncAttributeMaxDynamicSharedMemorySize, SMEM_BYTES);
    cudaFuncSetAttribute(mlp_kernel<1>, cudaFuncAttributeMaxDynamicSharedMemorySize, SMEM_BYTES);

    __half *ew1p, *ew2p, *nw1p, *nw2p;
    cudaGetSymbolAddress((void**)&ew1p, g_ew1h);
    cudaGetSymbolAddress((void**)&ew2p, g_ew2h);
    cudaGetSymbolAddress((void**)&nw1p, g_nw1h);
    cudaGetSymbolAddress((void**)&nw2p, g_nw2h);

    mlp_kernel<0><<<GRID_P, 256, SMEM_BYTES>>>(
        edge_attr, node_attr, global_attr, edge_index, batch,
        ew1p, ew2p, eb1, eb2, eg, eB, out_edge, E, E);

    mlp_kernel<1><<<GRID_P, 256, SMEM_BYTES>>>(
        node_attr, node_attr, global_attr, edge_index, batch,
        nw1p, nw2p, nb1, nb2, ng, nB, out_node, N, E);

    global_kernel<<<G, 128>>>(global_attr, gW1, gb1, gW2, gb2, out_glob);
}